// round 17
// baseline (speedup 1.0000x reference)
#include <cuda_runtime.h>
#include <cstdint>

#define NB      8
#define NCH     3
#define IMG     1024
#define PATCH   128
#define DPOS    256
#define KSEL    16
#define NSAMP   500
#define NKB     2          // k blocks
#define KPB     8          // k per block
#define PTB     16         // pt blocks (8 rows each)
#define BPB     (PTB * NCH)        // blocks per batch = 48
#define NBLK    (BPB * NB)         // total blocks = 384
#define WIBN    (BPB * 8)          // warps per batch = 384
#define EXTRA   (NSAMP - WIBN)     // 116 second-samples per batch

typedef unsigned long long ull;

// Persistent device scratch (zero-init at load; the LAST block re-zeroes
// everything -> clean state every graph replay).
__device__ __align__(16) int d_counts[NB][KSEL][DPOS];
__device__ int d_ind_done[NB];
__device__ int d_done;

// ---------------------------------------------------------------------------
// Threefry-2x32 (20 rounds), JAX partitionable layout.
// ---------------------------------------------------------------------------
__device__ __forceinline__ uint32_t threefry_bits(uint32_t ctr) {
    const uint32_t K0 = 0u;
    const uint32_t K1 = 42u;
    const uint32_t K2 = 0x1BD11BDAu ^ K0 ^ K1;
    uint32_t x0 = K0;
    uint32_t x1 = ctr + K1;
#define TFR(r) { x0 += x1; x1 = __funnelshift_l(x1, x1, (r)); x1 ^= x0; }
    TFR(13) TFR(15) TFR(26) TFR(6)
    x0 += K1; x1 += K2 + 1u;
    TFR(17) TFR(29) TFR(16) TFR(24)
    x0 += K2; x1 += K0 + 2u;
    TFR(13) TFR(15) TFR(26) TFR(6)
    x0 += K0; x1 += K1 + 3u;
    TFR(17) TFR(29) TFR(16) TFR(24)
    x0 += K1; x1 += K2 + 4u;
    TFR(13) TFR(15) TFR(26) TFR(6)
    x0 += K2; x1 += K0 + 5u;
#undef TFR
    return x0 ^ x1;
}

__device__ __forceinline__ float jax_normal(uint32_t f) {
    uint32_t bits = threefry_bits(f);
    float fl = __uint_as_float((bits >> 9) | 0x3f800000u) - 1.0f;  // [0,1)
    const float lo = -0.99999994f;
    float u = fl * 2.0f + lo;
    u = fmaxf(lo, u);
    return __uint_as_float(0x3fb504f3u) * erfinvf(u);   // sqrt(2)*erfinv
}

__device__ __forceinline__ uint32_t fkey(float v) {
    uint32_t u = __float_as_uint(v);
    return u ^ (uint32_t)(((int)u >> 31) | 0x80000000);
}

__device__ __forceinline__ ull fma2(ull a, ull b, ull c) {
    ull d;
    asm("fma.rn.f32x2 %0, %1, %2, %3;" : "=l"(d) : "l"(a), "l"(b), "l"(c));
    return d;
}

__device__ __forceinline__ ull dup2(float w) {
    uint32_t wb = __float_as_uint(w);
    return ((ull)wb << 32) | (ull)wb;
}

// one perturbed-top-16 sample: warp-collective, REDUX selection
__device__ __forceinline__ void do_sample(int b, int sample, const float* s_sh, int lane) {
    uint32_t base = (uint32_t)((b * NSAMP + sample) * DPOS);
    uint32_t ka[8];
#pragma unroll
    for (int j = 0; j < 8; j++) {
        int pos = j * 32 + lane;
        float z = jax_normal(base + (uint32_t)pos);
        ka[j] = fkey(__fadd_rn(s_sh[pos], __fmul_rn(z, 0.05f)));
    }
    int sel = 0;
    for (int it = 0; it < KSEL; it++) {
        uint32_t bk = 0u;
        int bp = 0x7fffffff;
#pragma unroll
        for (int j = 0; j < 8; j++) {
            int pos = j * 32 + lane;
            if (ka[j] > bk) { bk = ka[j]; bp = pos; }
        }
        uint32_t m = __reduce_max_sync(0xffffffffu, bk);
        unsigned cand = (bk == m) ? (unsigned)bp : 0x7fffffffu;
        int w = (int)__reduce_min_sync(0xffffffffu, cand);
        int sj = w >> 5;
        if (lane == (w & 31)) {
#pragma unroll
            for (int j = 0; j < 8; j++) if (j == sj) ka[j] = 0u;
        }
        if (lane == it) sel = w;
    }
    int r = 0;
#pragma unroll
    for (int j = 0; j < KSEL; j++) {
        int o = __shfl_sync(0xffffffffu, sel, j);
        if (o < sel) r++;
    }
    if (lane < KSEL) atomicAdd(&d_counts[b][r][sel], 1);
}

// ---------------------------------------------------------------------------
// Single fused kernel: indicator phase -> per-batch spin barrier ->
// compaction (NKB=2) -> assembly -> last-block cleanup.
// grid = (16 pt, 3 c, 8 b), block = 256. All 384 blocks co-resident
// (<= 3 blocks/SM by regs/smem/threads -> spin barrier is safe).
// ---------------------------------------------------------------------------
__global__ void __launch_bounds__(256, 3) fused_kernel(const float* __restrict__ x,
                                                       const float* __restrict__ scores,
                                                       float* __restrict__ out) {
    __shared__ float s_sh[DPOS];
    __shared__ float red[64];
    __shared__ int s_off[NKB + 1];
    __shared__ int s_pos[NKB * DPOS];
    __shared__ alignas(16) ull s_wt[NKB * DPOS][KPB];
    __shared__ int s_wcnt[8];
    __shared__ int s_base;
    __shared__ int s_last;

    int pt = blockIdx.x;          // 0..15 (8 rows each)
    int c  = blockIdx.y;
    int b  = blockIdx.z;
    int t  = threadIdx.x;
    int warp = t >> 5, lane = t & 31;

    // ---- phase 1: score normalization (per-block redundant; trivial) ----
    float v = __ldg(scores + b * DPOS + t);
    float mn = v, mx = v;
#pragma unroll
    for (int off = 16; off; off >>= 1) {
        mn = fminf(mn, __shfl_down_sync(0xffffffffu, mn, off));
        mx = fmaxf(mx, __shfl_down_sync(0xffffffffu, mx, off));
    }
    if (lane == 0) { red[warp] = mn; red[32 + warp] = mx; }
    __syncthreads();
    if (t == 0) {
        float m0 = red[0], m1 = red[32];
#pragma unroll
        for (int j = 1; j < 8; j++) { m0 = fminf(m0, red[j]); m1 = fmaxf(m1, red[32 + j]); }
        red[0] = m0; red[32] = m1;
    }
    __syncthreads();
    mn = red[0]; mx = red[32];
    float den = (mx - mn) + 1e-5f;
    s_sh[t] = __fdiv_rn(v - mn, den);
    __syncthreads();

    // ---- phase 2: indicator (warp = 1-2 samples of this block's batch) ----
    int bib = c * PTB + pt;            // block-in-batch 0..47
    int wib = bib * 8 + warp;          // warp-in-batch 0..383
    do_sample(b, wib, s_sh, lane);
    if ((wib % 3 == 0) && (wib / 3 < EXTRA))
        do_sample(b, WIBN + wib / 3, s_sh, lane);
    __syncthreads();
    __threadfence();
    if (t == 0) {
        atomicAdd(&d_ind_done[b], 1);
        while (atomicAdd(&d_ind_done[b], 0) < BPB) __nanosleep(128);
    }
    __syncthreads();
    __threadfence();

    // ---- phase 3: compaction (thread = position; ascending order) ----
    int flat = (t >> 4) * 65536 + (t & 15) * 64;
    if (t == 0) s_base = 0;
    __syncthreads();
    const float r500 = 1.0f / 500.0f;
#pragma unroll
    for (int kb = 0; kb < NKB; kb++) {
        int cc[KPB]; int any = 0;
#pragma unroll
        for (int j = 0; j < KPB; j++) {
            cc[j] = __ldcg(&d_counts[b][KPB * kb + j][t]);
            any |= cc[j];
        }
        unsigned m = __ballot_sync(0xffffffffu, any != 0);
        if (lane == 0) s_wcnt[warp] = __popc(m);
        __syncthreads();
        int basec = 0, ntot = 0;
#pragma unroll
        for (int wj = 0; wj < 8; wj++) {
            int wc = s_wcnt[wj];
            if (wj < warp) basec += wc;
            ntot += wc;
        }
        int base = s_base;
        if (t == 0) s_off[kb] = base;
        if (any) {
            int slot = base + basec + __popc(m & ((1u << lane) - 1u));
            s_pos[slot] = flat;
#pragma unroll
            for (int j = 0; j < KPB; j++)
                s_wt[slot][j] = dup2((float)cc[j] * r500);
        }
        __syncthreads();
        if (t == 0) s_base = base + ntot;
    }
    __syncthreads();
    if (t == 0) {
        s_off[NKB] = s_base;
        s_last = (atomicAdd(&d_done, 1) == NBLK - 1) ? 1 : 0;
    }
    __syncthreads();

    // ---- phase 4: assembly (thread = q-quad x row; LDG.128 per entry) ----
    int qt = t & 31;              // q quad: q = 4qt .. 4qt+3
    int pr = t >> 5;              // 0..7
    int p0 = pt * 8 + pr;
    int qc = 4 * qt - 32;         // multiple of 4
    int pc0 = p0 - 32;

    const float* xb = x + ((size_t)(b * NCH + c) << 20);

#pragma unroll
    for (int kb = 0; kb < NKB; kb++) {
        int e    = s_off[kb];
        int eend = s_off[kb + 1];

        ull accL[KPB], accH[KPB];
#pragma unroll
        for (int j = 0; j < KPB; j++) { accL[j] = 0ull; accH[j] = 0ull; }

#pragma unroll 1
        for (; e < eend; e++) {
            int f = s_pos[e];
            int col = (f & 1023) + qc;
            int rw  = (f >> 10) + pc0;
            ulonglong2 vq = make_ulonglong2(0ull, 0ull);
            if ((unsigned)col < 1024u && (unsigned)rw < 1024u)
                vq = *(const ulonglong2*)(xb + ((size_t)rw << 10) + col);
#pragma unroll
            for (int j = 0; j < KPB; j += 2) {
                ulonglong2 w = *(const ulonglong2*)&s_wt[e][j];
                accL[j]     = fma2(w.x, vq.x, accL[j]);
                accH[j]     = fma2(w.x, vq.y, accH[j]);
                accL[j + 1] = fma2(w.y, vq.x, accL[j + 1]);
                accH[j + 1] = fma2(w.y, vq.y, accH[j + 1]);
            }
        }

#pragma unroll
        for (int j = 0; j < KPB; j++) {
            int k = kb * KPB + j;
            float* op = out + (((size_t)((b * KSEL + k) * NCH + c)) << 14)
                            + ((size_t)p0 << 7) + 4 * qt;
            *(ulonglong2*)op = make_ulonglong2(accL[j], accH[j]);
        }
    }

    // ---- cleanup by globally-last block (all reads completed) ----
    if (s_last) {
        int4 z4 = make_int4(0, 0, 0, 0);
        int4* cp = (int4*)&d_counts[0][0][0];
        const int n4 = NB * KSEL * DPOS / 4;     // 8192 int4
#pragma unroll 1
        for (int i = t; i < n4; i += 256) cp[i] = z4;
        if (t < NB) d_ind_done[t] = 0;
        if (t == 0) d_done = 0;
    }
}

// ---------------------------------------------------------------------------
extern "C" void kernel_launch(void* const* d_in, const int* in_sizes, int n_in,
                              void* d_out, int out_size) {
    const float* x      = (const float*)d_in[0];
    const float* scores = (const float*)d_in[1];
    // scores tensor = 8*16*16 = 2048 elements; x_high = 25165824
    if (n_in >= 2 && in_sizes[0] == 2048) {
        const float* tmp = x; x = scores; scores = tmp;
    }
    float* out = (float*)d_out;

    fused_kernel<<<dim3(PTB, NCH, NB), 256>>>(x, scores, out);
}